// round 1
// baseline (speedup 1.0000x reference)
#include <cuda_runtime.h>
#include <cuda_bf16.h>

#define FH 32
#define FW 88
#define PPC 2816            // pixels per camera = FH*FW
#define NCAM 6
#define NPIX 16896          // NCAM*PPC
#define DD 41
#define CC 64
#define CIN 256
#define NOUT 105            // DD + CC
#define NVOX 16384
#define DPAD 44             // depth row padded to 16B multiple

// fp32 constants replicated exactly as the reference computes them:
// bx = float32(-51.2 + 0.4) = -50.8f  (python float64 -> f32)
// bxm = bx - dx/2 = -50.8f - 0.4f     (fp32 IEEE)
#define BXX (-50.8f - 0.4f)
#define BYY (-50.8f - 0.4f)
#define BZZ (-10.0f)

__device__ __align__(16) float g_depth[NPIX * DPAD];  // softmax depth, padded rows
__device__ __align__(16) float g_ctx[NPIX * CC];      // context features
__device__ __align__(16) float g_bev[NVOX * CC];      // scatter target [voxel][c]

// ---------------------------------------------------------------- K0: zero bev
__global__ void k_zero() {
    int i = blockIdx.x * blockDim.x + threadIdx.x;   // 262144 threads, exact
    reinterpret_cast<float4*>(g_bev)[i] = make_float4(0.f, 0.f, 0.f, 0.f);
}

// ------------------------------------------------- K1: GEMM + bias + softmax
__global__ void __launch_bounds__(128) k_feats(const float* __restrict__ x,
                                               const float* __restrict__ wd,
                                               const float* __restrict__ bd) {
    __shared__ float ws[NOUT][32];
    const int tid = threadIdx.x;
    const int pix = blockIdx.x * 128 + tid;          // grid = 132 CTAs, exact
    const int n = pix / PPC;
    const int p = pix - n * PPC;
    const float* xp = x + n * CIN * PPC + p;

    float acc[NOUT];
#pragma unroll
    for (int o = 0; o < NOUT; ++o) acc[o] = 0.f;

    // rolling x prefetch (4 values ahead)
    float c0 = xp[0 * PPC], c1 = xp[1 * PPC], c2 = xp[2 * PPC], c3 = xp[3 * PPC];

    for (int k0 = 0; k0 < CIN; k0 += 32) {
        __syncthreads();
        for (int i = tid; i < NOUT * 32; i += 128) {
            int o = i >> 5, kk = i & 31;
            ws[o][kk] = wd[o * CIN + k0 + kk];
        }
        __syncthreads();
#pragma unroll 1
        for (int kk = 0; kk < 32; kk += 4) {
            float n0, n1, n2, n3;
            int nk = k0 + kk + 4;
            if (nk < CIN) {
                n0 = xp[(nk + 0) * PPC];
                n1 = xp[(nk + 1) * PPC];
                n2 = xp[(nk + 2) * PPC];
                n3 = xp[(nk + 3) * PPC];
            }
#pragma unroll
            for (int o = 0; o < NOUT; ++o) acc[o] = fmaf(ws[o][kk + 0], c0, acc[o]);
#pragma unroll
            for (int o = 0; o < NOUT; ++o) acc[o] = fmaf(ws[o][kk + 1], c1, acc[o]);
#pragma unroll
            for (int o = 0; o < NOUT; ++o) acc[o] = fmaf(ws[o][kk + 2], c2, acc[o]);
#pragma unroll
            for (int o = 0; o < NOUT; ++o) acc[o] = fmaf(ws[o][kk + 3], c3, acc[o]);
            if (nk < CIN) { c0 = n0; c1 = n1; c2 = n2; c3 = n3; }
        }
    }

    // bias
#pragma unroll
    for (int o = 0; o < NOUT; ++o) acc[o] += bd[o];

    // softmax over first DD logits
    float m = acc[0];
#pragma unroll
    for (int o = 1; o < DD; ++o) m = fmaxf(m, acc[o]);
    float e[DPAD];
    float s = 0.f;
#pragma unroll
    for (int o = 0; o < DD; ++o) { e[o] = expf(acc[o] - m); s += e[o]; }
    e[41] = e[42] = e[43] = 0.f;
    float inv = 1.0f / s;

    float4* dp = reinterpret_cast<float4*>(g_depth + pix * DPAD);
#pragma unroll
    for (int i = 0; i < DPAD / 4; ++i)
        dp[i] = make_float4(e[4 * i] * inv, e[4 * i + 1] * inv,
                            e[4 * i + 2] * inv, e[4 * i + 3] * inv);

    float4* cp = reinterpret_cast<float4*>(g_ctx + pix * CC);
#pragma unroll
    for (int i = 0; i < CC / 4; ++i)
        cp[i] = make_float4(acc[DD + 4 * i], acc[DD + 4 * i + 1],
                            acc[DD + 4 * i + 2], acc[DD + 4 * i + 3]);
}

// -------------------------------------------------- 3x3 inverse via adjugate
__device__ __forceinline__ void inv3(const float* m, float* o) {
    float a = m[0], b = m[1], c = m[2];
    float d = m[3], e = m[4], f = m[5];
    float g = m[6], h = m[7], i = m[8];
    float A = (e * i - f * h);
    float B = -(d * i - f * g);
    float Cc = (d * h - e * g);
    float det = a * A + b * B + c * Cc;
    float id = 1.0f / det;
    o[0] = A * id;               o[1] = -(b * i - c * h) * id;  o[2] = (b * f - c * e) * id;
    o[3] = B * id;               o[4] = (a * i - c * g) * id;   o[5] = -(a * f - c * d) * id;
    o[6] = Cc * id;              o[7] = -(a * h - b * g) * id;  o[8] = (a * e - b * d) * id;
}

// ------------------------------------------- K2: geometry + voxel scatter-add
__global__ void __launch_bounds__(128) k_scatter(const float* __restrict__ rots,
                                                 const float* __restrict__ trans,
                                                 const float* __restrict__ intrins,
                                                 const float* __restrict__ post_rots,
                                                 const float* __restrict__ post_trans) {
    const int gw = (blockIdx.x * 128 + threadIdx.x) >> 5;  // warp-per-pixel
    const int lane = threadIdx.x & 31;
    if (gw >= NPIX) return;
    const int n = gw / PPC;
    const int hw = gw - n * PPC;
    const int h = hw / FW;
    const int w = hw - h * FW;

    float PR[9], Km[9], R[9], IPR[9], IK[9], M[9];
#pragma unroll
    for (int i = 0; i < 9; ++i) {
        PR[i] = post_rots[n * 9 + i];
        Km[i] = intrins[n * 9 + i];
        R[i]  = rots[n * 9 + i];
    }
    inv3(PR, IPR);
    inv3(Km, IK);
#pragma unroll
    for (int i = 0; i < 3; ++i)
#pragma unroll
        for (int j = 0; j < 3; ++j)
            M[i * 3 + j] = R[i * 3 + 0] * IK[0 + j] + R[i * 3 + 1] * IK[3 + j] +
                           R[i * 3 + 2] * IK[6 + j];
    const float t0 = trans[n * 3 + 0], t1 = trans[n * 3 + 1], t2 = trans[n * 3 + 2];
    const float pt0 = post_trans[n * 3 + 0], pt1 = post_trans[n * 3 + 1],
                pt2 = post_trans[n * 3 + 2];

    const float xs = (float)w * (1407.0f / 87.0f);
    const float ys = (float)h * (511.0f / 31.0f);
    const float q0 = xs - pt0, q1 = ys - pt1;

    auto rankOf = [&](float dv) -> int {
        float q2 = dv - pt2;
        float r0 = IPR[0] * q0 + IPR[1] * q1 + IPR[2] * q2;
        float r1 = IPR[3] * q0 + IPR[4] * q1 + IPR[5] * q2;
        float r2 = IPR[6] * q0 + IPR[7] * q1 + IPR[8] * q2;
        float s0 = r0 * r2, s1 = r1 * r2, s2 = r2;
        float px = M[0] * s0 + M[1] * s1 + M[2] * s2 + t0;
        float py = M[3] * s0 + M[4] * s1 + M[5] * s2 + t1;
        float pz = M[6] * s0 + M[7] * s1 + M[8] * s2 + t2;
        int gx = (int)((px - BXX) / 0.8f);
        int gy = (int)((py - BYY) / 0.8f);
        int gz = (int)((pz - BZZ) / 20.0f);
        return gx + gy * 128 + gz * 16384;   // exact reference rank (wraps included)
    };

    const int rank0 = rankOf(4.0f + (float)lane);          // depth index = lane
    const int rank1 = rankOf(36.0f + (float)lane);         // depth index = lane+32

    const float d0 = g_depth[gw * DPAD + lane];
    const float d1 = (lane + 32 < DD) ? g_depth[gw * DPAD + lane + 32] : 0.f;
    const float cx0 = g_ctx[gw * CC + lane];
    const float cx1 = g_ctx[gw * CC + 32 + lane];

#pragma unroll
    for (int di = 0; di < DD; ++di) {
        int r   = __shfl_sync(0xffffffffu, di < 32 ? rank0 : rank1, di & 31);
        float dw = __shfl_sync(0xffffffffu, di < 32 ? d0 : d1, di & 31);
        if ((unsigned)r < (unsigned)NVOX) {
            float* base = g_bev + r * CC;
            atomicAdd(base + lane, cx0 * dw);        // coalesced 128B
            atomicAdd(base + 32 + lane, cx1 * dw);   // coalesced 128B
        }
    }
}

// --------------------------------------- K3: [voxel][c] -> out[c][voxel] (C-major)
__global__ void k_transpose(float* __restrict__ out) {
    __shared__ float s[CC][33];
    const int v0 = blockIdx.x * 32;   // 512 CTAs, exact
    const int t = threadIdx.x;        // 256 threads
#pragma unroll
    for (int i = 0; i < 8; ++i) {
        int idx = t + i * 256;        // 0..2047
        int vl = idx >> 6, c = idx & 63;
        s[c][vl] = g_bev[(v0 + vl) * CC + c];
    }
    __syncthreads();
#pragma unroll
    for (int i = 0; i < 8; ++i) {
        int idx = t + i * 256;
        int c = idx >> 5, vl = idx & 31;
        out[c * NVOX + v0 + vl] = s[c][vl];
    }
}

extern "C" void kernel_launch(void* const* d_in, const int* in_sizes, int n_in,
                              void* d_out, int out_size) {
    const float* x          = (const float*)d_in[0];
    const float* rots       = (const float*)d_in[1];
    const float* trans      = (const float*)d_in[2];
    const float* intrins    = (const float*)d_in[3];
    const float* post_rots  = (const float*)d_in[4];
    const float* post_trans = (const float*)d_in[5];
    const float* w_depth    = (const float*)d_in[6];
    const float* b_depth    = (const float*)d_in[7];
    float* out = (float*)d_out;

    k_zero<<<1024, 256>>>();
    k_feats<<<NPIX / 128, 128>>>(x, w_depth, b_depth);
    k_scatter<<<NPIX / 4, 128>>>(rots, trans, intrins, post_rots, post_trans);
    k_transpose<<<NVOX / 32, 256>>>(out);
}

// round 2
// speedup vs baseline: 1.0873x; 1.0873x over previous
#include <cuda_runtime.h>
#include <cuda_bf16.h>

#define FH 32
#define FW 88
#define PPC 2816
#define NCAM 6
#define NPIX 16896
#define DD 41
#define CC 64
#define CIN 256
#define NOUT 105
#define NOUTP 112
#define NVOX 16384
#define DPAD 44

#define BXX (-50.8f - 0.4f)
#define BYY (-50.8f - 0.4f)
#define BZZ (-10.0f)

typedef unsigned long long ull;

__device__ __align__(16) float g_depth[NPIX * DPAD];
__device__ __align__(16) float g_ctx[NPIX * CC];
__device__ __align__(16) float g_bev[NVOX * CC];

__device__ __forceinline__ ull ffma2(ull a, ull b, ull c) {
    ull d;
    asm("fma.rn.f32x2 %0, %1, %2, %3;" : "=l"(d) : "l"(a), "l"(b), "l"(c));
    return d;
}

__device__ __forceinline__ void red4(float* addr, float4 v) {
    asm volatile("red.global.add.v4.f32 [%0], {%1,%2,%3,%4};"
                 :: "l"(addr), "f"(v.x), "f"(v.y), "f"(v.z), "f"(v.w) : "memory");
}

// ---------------------------------------------------------------- K0: zero bev
__global__ void k_zero() {
    int i = blockIdx.x * blockDim.x + threadIdx.x;
    reinterpret_cast<float4*>(g_bev)[i] = make_float4(0.f, 0.f, 0.f, 0.f);
}

// ---------------- K1: register-blocked GEMM (FFMA2) + bias + softmax epilogue
// CTA: 256 threads, tile = 112 outputs x 128 pixels, K staged in 16-chunks.
// thread tile: 7 outputs (og=tid>>4) x 8 pixels (pg=tid&15), pixels packed f32x2.
#define KCH 16
#define EPI_STRIDE 113

__global__ void __launch_bounds__(256) k_feats(const float* __restrict__ x,
                                               const float* __restrict__ wd,
                                               const float* __restrict__ bd) {
    extern __shared__ char smem[];
    float (*xs)[128]   = reinterpret_cast<float(*)[128]>(smem);            // 8192 B
    float2 (*wsd)[NOUTP] = reinterpret_cast<float2(*)[NOUTP]>(smem + 8192); // 14336 B
    float (*epi)[EPI_STRIDE] = reinterpret_cast<float(*)[EPI_STRIDE]>(smem); // 57856 B (reuse)

    const int tid = threadIdx.x;
    const int pg = tid & 15;
    const int og = tid >> 4;
    const int pix0 = blockIdx.x * 128;
    const int n = pix0 / PPC;            // 2816 % 128 == 0
    const int p0 = pix0 - n * PPC;
    const float* xb = x + n * CIN * PPC + p0;

    ull acc[7][4];
#pragma unroll
    for (int o = 0; o < 7; ++o)
#pragma unroll
        for (int j = 0; j < 4; ++j) acc[o][j] = 0ULL;

    for (int kc = 0; kc < CIN; kc += KCH) {
        __syncthreads();
        // fill x tile: 16 rows x 128 floats = 512 float4
#pragma unroll
        for (int i = tid; i < 512; i += 256) {
            int k = i >> 5, c4 = i & 31;
            reinterpret_cast<float4*>(&xs[k][0])[c4] =
                reinterpret_cast<const float4*>(xb + (kc + k) * PPC)[c4];
        }
        // fill duplicated weight pairs: 16 x 112
#pragma unroll
        for (int i = tid; i < KCH * NOUTP; i += 256) {
            int k = i / NOUTP, o = i - k * NOUTP;
            float w = (o < NOUT) ? wd[o * CIN + kc + k] : 0.f;
            wsd[k][o] = make_float2(w, w);
        }
        __syncthreads();
#pragma unroll
        for (int k = 0; k < KCH; ++k) {
            ull w2[7], x2[4];
#pragma unroll
            for (int o = 0; o < 7; ++o)
                w2[o] = *reinterpret_cast<const ull*>(&wsd[k][og * 7 + o]);
#pragma unroll
            for (int j = 0; j < 4; ++j)
                x2[j] = *reinterpret_cast<const ull*>(&xs[k][pg * 8 + 2 * j]);
#pragma unroll
            for (int o = 0; o < 7; ++o)
#pragma unroll
                for (int j = 0; j < 4; ++j)
                    acc[o][j] = ffma2(w2[o], x2[j], acc[o][j]);
        }
    }

    __syncthreads();   // done reading xs/wsd; epi overlays them
    // scatter accumulators into epi[pixel][output]
#pragma unroll
    for (int o = 0; o < 7; ++o) {
        int out = og * 7 + o;
        if (out < NOUT) {
#pragma unroll
            for (int j = 0; j < 4; ++j) {
                float2 f = *reinterpret_cast<float2*>(&acc[o][j]);
                int p = pg * 8 + 2 * j;
                epi[p][out] = f.x;
                epi[p + 1][out] = f.y;
            }
        }
    }
    __syncthreads();

    // softmax: one thread per pixel (tid < 128)
    if (tid < 128) {
        const int p = tid;
        float lg[DD];
#pragma unroll
        for (int o = 0; o < DD; ++o) lg[o] = epi[p][o] + bd[o];
        float m = lg[0];
#pragma unroll
        for (int o = 1; o < DD; ++o) m = fmaxf(m, lg[o]);
        float s = 0.f;
#pragma unroll
        for (int o = 0; o < DD; ++o) { lg[o] = expf(lg[o] - m); s += lg[o]; }
        float inv = 1.0f / s;
        float e[DPAD];
#pragma unroll
        for (int o = 0; o < DD; ++o) e[o] = lg[o] * inv;
        e[41] = e[42] = e[43] = 0.f;
        float4* dp = reinterpret_cast<float4*>(g_depth + (pix0 + p) * DPAD);
#pragma unroll
        for (int i = 0; i < DPAD / 4; ++i)
            dp[i] = make_float4(e[4 * i], e[4 * i + 1], e[4 * i + 2], e[4 * i + 3]);
    }

    // ctx: all 256 threads, 2048 float4
#pragma unroll
    for (int i = tid; i < 2048; i += 256) {
        int p = i >> 4, cq = i & 15;
        int c = DD + 4 * cq;
        float4 v;
        v.x = epi[p][c + 0] + bd[c + 0];
        v.y = epi[p][c + 1] + bd[c + 1];
        v.z = epi[p][c + 2] + bd[c + 2];
        v.w = epi[p][c + 3] + bd[c + 3];
        reinterpret_cast<float4*>(g_ctx + (pix0 + p) * CC)[cq] = v;
    }
}

// -------------------------------------------------- 3x3 inverse via adjugate
__device__ __forceinline__ void inv3(const float* m, float* o) {
    float a = m[0], b = m[1], c = m[2];
    float d = m[3], e = m[4], f = m[5];
    float g = m[6], h = m[7], i = m[8];
    float A = (e * i - f * h);
    float B = -(d * i - f * g);
    float Cc = (d * h - e * g);
    float det = a * A + b * B + c * Cc;
    float id = 1.0f / det;
    o[0] = A * id;  o[1] = -(b * i - c * h) * id;  o[2] = (b * f - c * e) * id;
    o[3] = B * id;  o[4] = (a * i - c * g) * id;   o[5] = -(a * f - c * d) * id;
    o[6] = Cc * id; o[7] = -(a * h - b * g) * id;  o[8] = (a * e - b * d) * id;
}

// ------------------------------------------- K2: geometry + voxel scatter-add
__global__ void __launch_bounds__(128) k_scatter(const float* __restrict__ rots,
                                                 const float* __restrict__ trans,
                                                 const float* __restrict__ intrins,
                                                 const float* __restrict__ post_rots,
                                                 const float* __restrict__ post_trans) {
    __shared__ int   s_rank[4][DPAD];
    __shared__ float s_w[4][DPAD];

    const int wl = threadIdx.x >> 5;                       // warp in CTA
    const int gw = (blockIdx.x * 128 + threadIdx.x) >> 5;  // pixel
    const int lane = threadIdx.x & 31;
    if (gw >= NPIX) return;
    const int n = gw / PPC;
    const int hw = gw - n * PPC;
    const int h = hw / FW;
    const int w = hw - h * FW;

    float PR[9], Km[9], R[9], IPR[9], IK[9], M[9];
#pragma unroll
    for (int i = 0; i < 9; ++i) {
        PR[i] = post_rots[n * 9 + i];
        Km[i] = intrins[n * 9 + i];
        R[i]  = rots[n * 9 + i];
    }
    inv3(PR, IPR);
    inv3(Km, IK);
#pragma unroll
    for (int i = 0; i < 3; ++i)
#pragma unroll
        for (int j = 0; j < 3; ++j)
            M[i * 3 + j] = R[i * 3 + 0] * IK[0 + j] + R[i * 3 + 1] * IK[3 + j] +
                           R[i * 3 + 2] * IK[6 + j];
    const float t0 = trans[n * 3 + 0], t1 = trans[n * 3 + 1], t2 = trans[n * 3 + 2];
    const float pt0 = post_trans[n * 3 + 0], pt1 = post_trans[n * 3 + 1],
                pt2 = post_trans[n * 3 + 2];

    const float xsc = (float)w * (1407.0f / 87.0f);
    const float ysc = (float)h * (511.0f / 31.0f);
    const float q0 = xsc - pt0, q1 = ysc - pt1;

    auto rankOf = [&](float dv) -> int {
        float q2 = dv - pt2;
        float r0 = IPR[0] * q0 + IPR[1] * q1 + IPR[2] * q2;
        float r1 = IPR[3] * q0 + IPR[4] * q1 + IPR[5] * q2;
        float r2 = IPR[6] * q0 + IPR[7] * q1 + IPR[8] * q2;
        float s0 = r0 * r2, s1 = r1 * r2, s2 = r2;
        float px = M[0] * s0 + M[1] * s1 + M[2] * s2 + t0;
        float py = M[3] * s0 + M[4] * s1 + M[5] * s2 + t1;
        float pz = M[6] * s0 + M[7] * s1 + M[8] * s2 + t2;
        int gx = (int)((px - BXX) / 0.8f);
        int gy = (int)((py - BYY) / 0.8f);
        int gz = (int)((pz - BZZ) / 20.0f);
        return gx + gy * 128 + gz * 16384;
    };

    // lane holds bins lane and lane+32
    s_rank[wl][lane] = rankOf(4.0f + (float)lane);
    s_w[wl][lane]    = g_depth[gw * DPAD + lane];
    if (lane < 12) {
        s_rank[wl][lane + 32] = (lane < 9) ? rankOf(36.0f + (float)lane) : -1;
        s_w[wl][lane + 32]    = g_depth[gw * DPAD + 32 + lane];
    }
    __syncwarp();

    const int cl = lane & 15;
    const int half = lane >> 4;
    const float4 cx = reinterpret_cast<const float4*>(g_ctx + gw * CC)[cl];
    float* bevc = g_bev + cl * 4;

#pragma unroll
    for (int it = 0; it < 21; ++it) {
        int b = 2 * it + half;
        int r = s_rank[wl][b];
        float dw = s_w[wl][b];
        if ((unsigned)r < (unsigned)NVOX) {
            float4 v = make_float4(cx.x * dw, cx.y * dw, cx.z * dw, cx.w * dw);
            red4(bevc + r * CC, v);
        }
    }
}

// --------------------------------------- K3: [voxel][c] -> out[c][voxel]
__global__ void k_transpose(float* __restrict__ out) {
    __shared__ float s[CC][33];
    const int v0 = blockIdx.x * 32;
    const int t = threadIdx.x;
#pragma unroll
    for (int i = 0; i < 8; ++i) {
        int idx = t + i * 256;
        int vl = idx >> 6, c = idx & 63;
        s[c][vl] = g_bev[(v0 + vl) * CC + c];
    }
    __syncthreads();
#pragma unroll
    for (int i = 0; i < 8; ++i) {
        int idx = t + i * 256;
        int c = idx >> 5, vl = idx & 31;
        out[c * NVOX + v0 + vl] = s[c][vl];
    }
}

extern "C" void kernel_launch(void* const* d_in, const int* in_sizes, int n_in,
                              void* d_out, int out_size) {
    const float* x          = (const float*)d_in[0];
    const float* rots       = (const float*)d_in[1];
    const float* trans      = (const float*)d_in[2];
    const float* intrins    = (const float*)d_in[3];
    const float* post_rots  = (const float*)d_in[4];
    const float* post_trans = (const float*)d_in[5];
    const float* w_depth    = (const float*)d_in[6];
    const float* b_depth    = (const float*)d_in[7];
    float* out = (float*)d_out;

    const int feats_smem = 128 * EPI_STRIDE * sizeof(float);  // 57856
    cudaFuncSetAttribute(k_feats, cudaFuncAttributeMaxDynamicSharedMemorySize,
                         feats_smem);

    k_zero<<<1024, 256>>>();
    k_feats<<<NPIX / 128, 128 * 2, feats_smem>>>(x, w_depth, b_depth);
    k_scatter<<<NPIX / 4, 128>>>(rots, trans, intrins, post_rots, post_trans);
    k_transpose<<<NVOX / 32, 256>>>(out);
}

// round 3
// speedup vs baseline: 1.1186x; 1.0288x over previous
#include <cuda_runtime.h>
#include <cuda_bf16.h>

#define FH 32
#define FW 88
#define PPC 2816
#define NCAM 6
#define NPIX 16896
#define DD 41
#define CC 64
#define CIN 256
#define NOUT 105
#define NOUTP 112
#define NVOX 16384
#define DPAD 44

#define BXX (-50.8f - 0.4f)
#define BYY (-50.8f - 0.4f)
#define BZZ (-10.0f)

typedef unsigned long long ull;

__device__ __align__(16) float g_depth[NPIX * DPAD];
__device__ __align__(16) float g_ctx[NPIX * CC];
__device__ __align__(16) float g_bev[NVOX * CC];

__device__ __forceinline__ ull ffma2(ull a, ull b, ull c) {
    ull d;
    asm("fma.rn.f32x2 %0, %1, %2, %3;" : "=l"(d) : "l"(a), "l"(b), "l"(c));
    return d;
}

__device__ __forceinline__ void red4(float* addr, float4 v) {
    asm volatile("red.global.add.v4.f32 [%0], {%1,%2,%3,%4};"
                 :: "l"(addr), "f"(v.x), "f"(v.y), "f"(v.z), "f"(v.w) : "memory");
}

// ---------------------------------------------------------------- K0: zero bev
__global__ void k_zero() {
    int i = blockIdx.x * blockDim.x + threadIdx.x;
    reinterpret_cast<float4*>(g_bev)[i] = make_float4(0.f, 0.f, 0.f, 0.f);
}

// ---------------- K1: register-blocked GEMM (FFMA2) + bias + softmax epilogue
// CTA: 256 threads, tile = 112 outputs x 128 pixels, K staged in 16-chunks.
// thread tile: 7 outputs (og=tid>>4) x 8 pixels (pg=tid&15), pixels packed f32x2.
// xs rows padded: physical col pc = c + 2*(c>>5) -> x2 LDS.64 bank-conflict-free.
#define KCH 16
#define XROW 136              // 128 data + 4 pads of 2 floats
#define EPI_STRIDE 113

__global__ void __launch_bounds__(256) k_feats(const float* __restrict__ x,
                                               const float* __restrict__ wd,
                                               const float* __restrict__ bd) {
    extern __shared__ char smem[];
    float* xs = reinterpret_cast<float*>(smem);                             // 16*136*4 = 8704 B
    float2 (*wsd)[NOUTP] = reinterpret_cast<float2(*)[NOUTP]>(smem + 8704); // 14336 B
    float (*epi)[EPI_STRIDE] = reinterpret_cast<float(*)[EPI_STRIDE]>(smem); // 57856 B (reuse)

    const int tid = threadIdx.x;
    const int pg = tid & 15;
    const int og = tid >> 4;
    const int pix0 = blockIdx.x * 128;
    const int n = pix0 / PPC;            // 2816 % 128 == 0
    const int p0 = pix0 - n * PPC;
    const float* xb = x + n * CIN * PPC + p0;

    const int pc0 = pg * 8 + 2 * (pg >> 2);   // swizzled base col for this thread

    ull acc[7][4];
#pragma unroll
    for (int o = 0; o < 7; ++o)
#pragma unroll
        for (int j = 0; j < 4; ++j) acc[o][j] = 0ULL;

    for (int kc = 0; kc < CIN; kc += KCH) {
        __syncthreads();
        // fill x tile: 16 rows x 128 floats as float2 with pad swizzle
#pragma unroll
        for (int i = tid; i < 1024; i += 256) {
            int k = i >> 6, c2 = i & 63;
            int pc = 2 * c2 + 2 * (c2 >> 4);
            *reinterpret_cast<float2*>(&xs[k * XROW + pc]) =
                *reinterpret_cast<const float2*>(xb + (kc + k) * PPC + 2 * c2);
        }
        // fill duplicated weight pairs: 16 x 112
#pragma unroll
        for (int i = tid; i < KCH * NOUTP; i += 256) {
            int k = i / NOUTP, o = i - k * NOUTP;
            float w = (o < NOUT) ? wd[o * CIN + kc + k] : 0.f;
            wsd[k][o] = make_float2(w, w);
        }
        __syncthreads();
#pragma unroll
        for (int k = 0; k < KCH; ++k) {
            ull w2[7], x2[4];
            const float* xr = xs + k * XROW + pc0;
#pragma unroll
            for (int o = 0; o < 7; ++o)
                w2[o] = *reinterpret_cast<const ull*>(&wsd[k][og * 7 + o]);
#pragma unroll
            for (int j = 0; j < 4; ++j)
                x2[j] = *reinterpret_cast<const ull*>(xr + 2 * j);
#pragma unroll
            for (int o = 0; o < 7; ++o)
#pragma unroll
                for (int j = 0; j < 4; ++j)
                    acc[o][j] = ffma2(w2[o], x2[j], acc[o][j]);
        }
    }

    __syncthreads();   // done reading xs/wsd; epi overlays them
#pragma unroll
    for (int o = 0; o < 7; ++o) {
        int out = og * 7 + o;
        if (out < NOUT) {
#pragma unroll
            for (int j = 0; j < 4; ++j) {
                float2 f = *reinterpret_cast<float2*>(&acc[o][j]);
                int p = pg * 8 + 2 * j;
                epi[p][out] = f.x;
                epi[p + 1][out] = f.y;
            }
        }
    }
    __syncthreads();

    // softmax: one thread per pixel (tid < 128)
    if (tid < 128) {
        const int p = tid;
        float lg[DD];
#pragma unroll
        for (int o = 0; o < DD; ++o) lg[o] = epi[p][o] + bd[o];
        float m = lg[0];
#pragma unroll
        for (int o = 1; o < DD; ++o) m = fmaxf(m, lg[o]);
        float s = 0.f;
#pragma unroll
        for (int o = 0; o < DD; ++o) { lg[o] = expf(lg[o] - m); s += lg[o]; }
        float inv = 1.0f / s;
        float e[DPAD];
#pragma unroll
        for (int o = 0; o < DD; ++o) e[o] = lg[o] * inv;
        e[41] = e[42] = e[43] = 0.f;
        float4* dp = reinterpret_cast<float4*>(g_depth + (pix0 + p) * DPAD);
#pragma unroll
        for (int i = 0; i < DPAD / 4; ++i)
            dp[i] = make_float4(e[4 * i], e[4 * i + 1], e[4 * i + 2], e[4 * i + 3]);
    }

    // ctx: all 256 threads, 2048 float4
#pragma unroll
    for (int i = tid; i < 2048; i += 256) {
        int p = i >> 4, cq = i & 15;
        int c = DD + 4 * cq;
        float4 v;
        v.x = epi[p][c + 0] + bd[c + 0];
        v.y = epi[p][c + 1] + bd[c + 1];
        v.z = epi[p][c + 2] + bd[c + 2];
        v.w = epi[p][c + 3] + bd[c + 3];
        reinterpret_cast<float4*>(g_ctx + (pix0 + p) * CC)[cq] = v;
    }
}

// -------------------------------------------------- 3x3 inverse via adjugate
__device__ __forceinline__ void inv3(const float* m, float* o) {
    float a = m[0], b = m[1], c = m[2];
    float d = m[3], e = m[4], f = m[5];
    float g = m[6], h = m[7], i = m[8];
    float A = (e * i - f * h);
    float B = -(d * i - f * g);
    float Cc = (d * h - e * g);
    float det = a * A + b * B + c * Cc;
    float id = 1.0f / det;
    o[0] = A * id;  o[1] = -(b * i - c * h) * id;  o[2] = (b * f - c * e) * id;
    o[3] = B * id;  o[4] = (a * i - c * g) * id;   o[5] = -(a * f - c * d) * id;
    o[6] = Cc * id; o[7] = -(a * h - b * g) * id;  o[8] = (a * e - b * d) * id;
}

// ------------------------------------------- K2: geometry + voxel scatter-add
__global__ void __launch_bounds__(128) k_scatter(const float* __restrict__ rots,
                                                 const float* __restrict__ trans,
                                                 const float* __restrict__ intrins,
                                                 const float* __restrict__ post_rots,
                                                 const float* __restrict__ post_trans) {
    __shared__ int   s_rank[4][DPAD];
    __shared__ float s_w[4][DPAD];

    const int wl = threadIdx.x >> 5;
    const int gw = (blockIdx.x * 128 + threadIdx.x) >> 5;
    const int lane = threadIdx.x & 31;
    if (gw >= NPIX) return;
    const int n = gw / PPC;
    const int hw = gw - n * PPC;
    const int h = hw / FW;
    const int w = hw - h * FW;

    float PR[9], Km[9], R[9], IPR[9], IK[9], M[9];
#pragma unroll
    for (int i = 0; i < 9; ++i) {
        PR[i] = post_rots[n * 9 + i];
        Km[i] = intrins[n * 9 + i];
        R[i]  = rots[n * 9 + i];
    }
    inv3(PR, IPR);
    inv3(Km, IK);
#pragma unroll
    for (int i = 0; i < 3; ++i)
#pragma unroll
        for (int j = 0; j < 3; ++j)
            M[i * 3 + j] = R[i * 3 + 0] * IK[0 + j] + R[i * 3 + 1] * IK[3 + j] +
                           R[i * 3 + 2] * IK[6 + j];
    const float t0 = trans[n * 3 + 0], t1 = trans[n * 3 + 1], t2 = trans[n * 3 + 2];
    const float pt0 = post_trans[n * 3 + 0], pt1 = post_trans[n * 3 + 1],
                pt2 = post_trans[n * 3 + 2];

    const float xsc = (float)w * (1407.0f / 87.0f);
    const float ysc = (float)h * (511.0f / 31.0f);
    const float q0 = xsc - pt0, q1 = ysc - pt1;

    auto rankOf = [&](float dv) -> int {
        float q2 = dv - pt2;
        float r0 = IPR[0] * q0 + IPR[1] * q1 + IPR[2] * q2;
        float r1 = IPR[3] * q0 + IPR[4] * q1 + IPR[5] * q2;
        float r2 = IPR[6] * q0 + IPR[7] * q1 + IPR[8] * q2;
        float s0 = r0 * r2, s1 = r1 * r2, s2 = r2;
        float px = M[0] * s0 + M[1] * s1 + M[2] * s2 + t0;
        float py = M[3] * s0 + M[4] * s1 + M[5] * s2 + t1;
        float pz = M[6] * s0 + M[7] * s1 + M[8] * s2 + t2;
        int gx = (int)((px - BXX) / 0.8f);
        int gy = (int)((py - BYY) / 0.8f);
        int gz = (int)((pz - BZZ) / 20.0f);
        return gx + gy * 128 + gz * 16384;
    };

    s_rank[wl][lane] = rankOf(4.0f + (float)lane);
    s_w[wl][lane]    = g_depth[gw * DPAD + lane];
    if (lane < 12) {
        s_rank[wl][lane + 32] = (lane < 9) ? rankOf(36.0f + (float)lane) : -1;
        s_w[wl][lane + 32]    = g_depth[gw * DPAD + 32 + lane];
    }
    __syncwarp();

    const int cl = lane & 15;
    const int half = lane >> 4;
    const float4 cx = reinterpret_cast<const float4*>(g_ctx + gw * CC)[cl];
    float* bevc = g_bev + cl * 4;

#pragma unroll
    for (int it = 0; it < 21; ++it) {
        int b = 2 * it + half;
        int r = s_rank[wl][b];
        float dw = s_w[wl][b];
        if ((unsigned)r < (unsigned)NVOX) {
            float4 v = make_float4(cx.x * dw, cx.y * dw, cx.z * dw, cx.w * dw);
            red4(bevc + r * CC, v);
        }
    }
}

// --------------------------------------- K3: [voxel][c] -> out[c][voxel], float4
__global__ void __launch_bounds__(256) k_transpose(float* __restrict__ out) {
    __shared__ float s[CC][36];
    const int v0 = blockIdx.x * 32;
    const int t = threadIdx.x;
#pragma unroll
    for (int i = 0; i < 2; ++i) {
        int idx = t + i * 256;              // 0..511
        int cq = idx & 15, v = idx >> 4;    // coalesced 256B per 16 lanes
        float4 val = reinterpret_cast<const float4*>(g_bev)[(v0 + v) * 16 + cq];
        s[4 * cq + 0][v] = val.x;
        s[4 * cq + 1][v] = val.y;
        s[4 * cq + 2][v] = val.z;
        s[4 * cq + 3][v] = val.w;
    }
    __syncthreads();
#pragma unroll
    for (int i = 0; i < 2; ++i) {
        int idx = t + i * 256;
        int c = idx >> 3, w = idx & 7;
        float4 val = *reinterpret_cast<const float4*>(&s[c][4 * w]);
        reinterpret_cast<float4*>(out)[c * (NVOX / 4) + (v0 >> 2) + w] = val;
    }
}

extern "C" void kernel_launch(void* const* d_in, const int* in_sizes, int n_in,
                              void* d_out, int out_size) {
    const float* x          = (const float*)d_in[0];
    const float* rots       = (const float*)d_in[1];
    const float* trans      = (const float*)d_in[2];
    const float* intrins    = (const float*)d_in[3];
    const float* post_rots  = (const float*)d_in[4];
    const float* post_trans = (const float*)d_in[5];
    const float* w_depth    = (const float*)d_in[6];
    const float* b_depth    = (const float*)d_in[7];
    float* out = (float*)d_out;

    const int feats_smem = 128 * EPI_STRIDE * sizeof(float);  // 57856
    cudaFuncSetAttribute(k_feats, cudaFuncAttributeMaxDynamicSharedMemorySize,
                         feats_smem);

    k_zero<<<1024, 256>>>();
    k_feats<<<NPIX / 128, 256, feats_smem>>>(x, w_depth, b_depth);
    k_scatter<<<NPIX / 4, 128>>>(rots, trans, intrins, post_rots, post_trans);
    k_transpose<<<NVOX / 32, 256>>>(out);
}

// round 4
// speedup vs baseline: 1.1236x; 1.0045x over previous
#include <cuda_runtime.h>
#include <cuda_bf16.h>
#include <cstdint>

#define FH 32
#define FW 88
#define PPC 2816
#define NCAM 6
#define NPIX 16896
#define DD 41
#define CC 64
#define CIN 256
#define NOUT 105
#define NOUTP 112
#define NVOX 16384
#define DPAD 44

#define BXX (-50.8f - 0.4f)
#define BYY (-50.8f - 0.4f)
#define BZZ (-10.0f)

typedef unsigned long long ull;

__device__ __align__(16) float g_depth[NPIX * DPAD];
__device__ __align__(16) float g_ctx[NPIX * CC];
__device__ __align__(16) float g_bev[NVOX * CC];

__device__ __forceinline__ ull ffma2(ull a, ull b, ull c) {
    ull d;
    asm("fma.rn.f32x2 %0, %1, %2, %3;" : "=l"(d) : "l"(a), "l"(b), "l"(c));
    return d;
}

__device__ __forceinline__ void red4(float* addr, float4 v) {
    asm volatile("red.global.add.v4.f32 [%0], {%1,%2,%3,%4};"
                 :: "l"(addr), "f"(v.x), "f"(v.y), "f"(v.z), "f"(v.w) : "memory");
}

__device__ __forceinline__ void cp8(uint32_t s, const float* g) {
    asm volatile("cp.async.ca.shared.global [%0], [%1], 8;" :: "r"(s), "l"(g));
}
__device__ __forceinline__ uint32_t s2u(const void* p) {
    return (uint32_t)__cvta_generic_to_shared(p);
}

// ---------------------------------------------------------------- K0: zero bev
__global__ void k_zero() {
    int i = blockIdx.x * blockDim.x + threadIdx.x;
    reinterpret_cast<float4*>(g_bev)[i] = make_float4(0.f, 0.f, 0.f, 0.f);
}

// ---------------- K1: pipelined register-blocked GEMM (FFMA2) + softmax
// CTA 256 threads, tile 112 out x 128 px, K in 16-chunks, double-buffered.
#define KCH 16
#define XROW 136                       // 128 + pad swizzle
#define XS_BYTES (KCH * XROW * 4)      // 8704
#define WS_BYTES (KCH * NOUTP * 8)     // 14336
#define STAGE_BYTES (XS_BYTES + WS_BYTES)  // 23040
#define EPI_STRIDE 113
#define FEATS_SMEM (128 * EPI_STRIDE * 4)  // 57856 (> 2*STAGE_BYTES)

__global__ void __launch_bounds__(256) k_feats(const float* __restrict__ x,
                                               const float* __restrict__ wd,
                                               const float* __restrict__ bd) {
    extern __shared__ char smem[];
    float (*epi)[EPI_STRIDE] = reinterpret_cast<float(*)[EPI_STRIDE]>(smem);

    const int tid = threadIdx.x;
    const int pg = tid & 15;
    const int og = tid >> 4;
    const int pix0 = blockIdx.x * 128;
    const int n = pix0 / PPC;
    const int p0 = pix0 - n * PPC;
    const float* xb = x + n * CIN * PPC + p0;

    const int pc0 = pg * 8 + 2 * (pg >> 2);

    // per-thread chunk-invariant fill coordinates
    int xk[4], xc[4];                 // xs fill: 4 x 8B
#pragma unroll
    for (int r = 0; r < 4; ++r) {
        int i = tid + 256 * r;
        xk[r] = i >> 6;
        xc[r] = i & 63;
    }
    int wk[7], wo[7];                 // w fill: 7 scalars
#pragma unroll
    for (int r = 0; r < 7; ++r) {
        int i = tid + 256 * r;
        wk[r] = i / NOUTP;
        wo[r] = i - wk[r] * NOUTP;
    }

    ull acc[7][4];
#pragma unroll
    for (int o = 0; o < 7; ++o)
#pragma unroll
        for (int j = 0; j < 4; ++j) acc[o][j] = 0ULL;

    // ---- prologue: fill stage 0 (chunk 0)
    {
        char* st = smem;
#pragma unroll
        for (int r = 0; r < 4; ++r) {
            int pc = 2 * xc[r] + 2 * (xc[r] >> 4);
            cp8(s2u(st + (xk[r] * XROW + pc) * 4), xb + xk[r] * PPC + 2 * xc[r]);
        }
        float2* wsd = reinterpret_cast<float2*>(st + XS_BYTES);
#pragma unroll
        for (int r = 0; r < 7; ++r) {
            float w = (wo[r] < NOUT) ? wd[wo[r] * CIN + wk[r]] : 0.f;
            wsd[wk[r] * NOUTP + wo[r]] = make_float2(w, w);
        }
        asm volatile("cp.async.commit_group;");
        asm volatile("cp.async.wait_group 0;");
        __syncthreads();
    }

    for (int kc = 0; kc < CIN; kc += KCH) {
        char* cur = smem + ((kc >> 4) & 1) * STAGE_BYTES;
        char* nxt = smem + (~(kc >> 4) & 1) * STAGE_BYTES;
        const bool more = (kc + KCH) < CIN;

        float wv[7];
        if (more) {
            const float* xn = xb + (kc + KCH) * PPC;
#pragma unroll
            for (int r = 0; r < 4; ++r) {
                int pc = 2 * xc[r] + 2 * (xc[r] >> 4);
                cp8(s2u(nxt + (xk[r] * XROW + pc) * 4), xn + xk[r] * PPC + 2 * xc[r]);
            }
#pragma unroll
            for (int r = 0; r < 7; ++r)
                wv[r] = (wo[r] < NOUT) ? wd[wo[r] * CIN + kc + KCH + wk[r]] : 0.f;
        }

        const float* xs = reinterpret_cast<const float*>(cur);
        const float2* wsd = reinterpret_cast<const float2*>(cur + XS_BYTES);
#pragma unroll
        for (int k = 0; k < KCH; ++k) {
            ull w2[7], x2[4];
            const float* xr = xs + k * XROW + pc0;
#pragma unroll
            for (int o = 0; o < 7; ++o)
                w2[o] = *reinterpret_cast<const ull*>(&wsd[k * NOUTP + og * 7 + o]);
#pragma unroll
            for (int j = 0; j < 4; ++j)
                x2[j] = *reinterpret_cast<const ull*>(xr + 2 * j);
#pragma unroll
            for (int o = 0; o < 7; ++o)
#pragma unroll
                for (int j = 0; j < 4; ++j)
                    acc[o][j] = ffma2(w2[o], x2[j], acc[o][j]);
        }

        if (more) {
            float2* wsn = reinterpret_cast<float2*>(nxt + XS_BYTES);
#pragma unroll
            for (int r = 0; r < 7; ++r)
                wsn[wk[r] * NOUTP + wo[r]] = make_float2(wv[r], wv[r]);
        }
        asm volatile("cp.async.commit_group;");
        asm volatile("cp.async.wait_group 0;");
        __syncthreads();
    }

    // ---- epilogue (epi overlays stage buffers)
#pragma unroll
    for (int o = 0; o < 7; ++o) {
        int out = og * 7 + o;
        if (out < NOUT) {
#pragma unroll
            for (int j = 0; j < 4; ++j) {
                float2 f = *reinterpret_cast<float2*>(&acc[o][j]);
                int p = pg * 8 + 2 * j;
                epi[p][out] = f.x;
                epi[p + 1][out] = f.y;
            }
        }
    }
    __syncthreads();

    if (tid < 128) {
        const int p = tid;
        float lg[DD];
#pragma unroll
        for (int o = 0; o < DD; ++o) lg[o] = epi[p][o] + bd[o];
        float m = lg[0];
#pragma unroll
        for (int o = 1; o < DD; ++o) m = fmaxf(m, lg[o]);
        float s = 0.f;
#pragma unroll
        for (int o = 0; o < DD; ++o) { lg[o] = expf(lg[o] - m); s += lg[o]; }
        float inv = 1.0f / s;
        float e[DPAD];
#pragma unroll
        for (int o = 0; o < DD; ++o) e[o] = lg[o] * inv;
        e[41] = e[42] = e[43] = 0.f;
        float4* dp = reinterpret_cast<float4*>(g_depth + (pix0 + p) * DPAD);
#pragma unroll
        for (int i = 0; i < DPAD / 4; ++i)
            dp[i] = make_float4(e[4 * i], e[4 * i + 1], e[4 * i + 2], e[4 * i + 3]);
    }

#pragma unroll
    for (int i = tid; i < 2048; i += 256) {
        int p = i >> 4, cq = i & 15;
        int c = DD + 4 * cq;
        float4 v;
        v.x = epi[p][c + 0] + bd[c + 0];
        v.y = epi[p][c + 1] + bd[c + 1];
        v.z = epi[p][c + 2] + bd[c + 2];
        v.w = epi[p][c + 3] + bd[c + 3];
        reinterpret_cast<float4*>(g_ctx + (pix0 + p) * CC)[cq] = v;
    }
}

// -------------------------------------------------- 3x3 inverse via adjugate
__device__ __forceinline__ void inv3(const float* m, float* o) {
    float a = m[0], b = m[1], c = m[2];
    float d = m[3], e = m[4], f = m[5];
    float g = m[6], h = m[7], i = m[8];
    float A = (e * i - f * h);
    float B = -(d * i - f * g);
    float Cc = (d * h - e * g);
    float det = a * A + b * B + c * Cc;
    float id = 1.0f / det;
    o[0] = A * id;  o[1] = -(b * i - c * h) * id;  o[2] = (b * f - c * e) * id;
    o[3] = B * id;  o[4] = (a * i - c * g) * id;   o[5] = -(a * f - c * d) * id;
    o[6] = Cc * id; o[7] = -(a * h - b * g) * id;  o[8] = (a * e - b * d) * id;
}

// ------------------------------------------- K2: geometry + voxel scatter-add
__global__ void __launch_bounds__(128) k_scatter(const float* __restrict__ rots,
                                                 const float* __restrict__ trans,
                                                 const float* __restrict__ intrins,
                                                 const float* __restrict__ post_rots,
                                                 const float* __restrict__ post_trans) {
    __shared__ int   s_rank[4][DPAD];
    __shared__ float s_w[4][DPAD];

    const int wl = threadIdx.x >> 5;
    const int gw = (blockIdx.x * 128 + threadIdx.x) >> 5;
    const int lane = threadIdx.x & 31;
    if (gw >= NPIX) return;
    const int n = gw / PPC;
    const int hw = gw - n * PPC;
    const int h = hw / FW;
    const int w = hw - h * FW;

    float PR[9], Km[9], R[9], IPR[9], IK[9], M[9];
#pragma unroll
    for (int i = 0; i < 9; ++i) {
        PR[i] = post_rots[n * 9 + i];
        Km[i] = intrins[n * 9 + i];
        R[i]  = rots[n * 9 + i];
    }
    inv3(PR, IPR);
    inv3(Km, IK);
#pragma unroll
    for (int i = 0; i < 3; ++i)
#pragma unroll
        for (int j = 0; j < 3; ++j)
            M[i * 3 + j] = R[i * 3 + 0] * IK[0 + j] + R[i * 3 + 1] * IK[3 + j] +
                           R[i * 3 + 2] * IK[6 + j];
    const float t0 = trans[n * 3 + 0], t1 = trans[n * 3 + 1], t2 = trans[n * 3 + 2];
    const float pt0 = post_trans[n * 3 + 0], pt1 = post_trans[n * 3 + 1],
                pt2 = post_trans[n * 3 + 2];

    const float xsc = (float)w * (1407.0f / 87.0f);
    const float ysc = (float)h * (511.0f / 31.0f);
    const float q0 = xsc - pt0, q1 = ysc - pt1;

    auto rankOf = [&](float dv) -> int {
        float q2 = dv - pt2;
        float r0 = IPR[0] * q0 + IPR[1] * q1 + IPR[2] * q2;
        float r1 = IPR[3] * q0 + IPR[4] * q1 + IPR[5] * q2;
        float r2 = IPR[6] * q0 + IPR[7] * q1 + IPR[8] * q2;
        float s0 = r0 * r2, s1 = r1 * r2, s2 = r2;
        float px = M[0] * s0 + M[1] * s1 + M[2] * s2 + t0;
        float py = M[3] * s0 + M[4] * s1 + M[5] * s2 + t1;
        float pz = M[6] * s0 + M[7] * s1 + M[8] * s2 + t2;
        int gx = (int)((px - BXX) / 0.8f);
        int gy = (int)((py - BYY) / 0.8f);
        int gz = (int)((pz - BZZ) / 20.0f);
        return gx + gy * 128 + gz * 16384;
    };

    s_rank[wl][lane] = rankOf(4.0f + (float)lane);
    s_w[wl][lane]    = g_depth[gw * DPAD + lane];
    if (lane < 12) {
        s_rank[wl][lane + 32] = (lane < 9) ? rankOf(36.0f + (float)lane) : -1;
        s_w[wl][lane + 32]    = g_depth[gw * DPAD + 32 + lane];
    }
    __syncwarp();

    const int cl = lane & 15;
    const int half = lane >> 4;
    const float4 cx = reinterpret_cast<const float4*>(g_ctx + gw * CC)[cl];
    float* bevc = g_bev + cl * 4;

#pragma unroll
    for (int it = 0; it < 21; ++it) {
        int b = 2 * it + half;
        int r = s_rank[wl][b];
        float dw = s_w[wl][b];
        if ((unsigned)r < (unsigned)NVOX) {
            float4 v = make_float4(cx.x * dw, cx.y * dw, cx.z * dw, cx.w * dw);
            red4(bevc + r * CC, v);
        }
    }
}

// --------------------------------------- K3: [voxel][c] -> out[c][voxel], float4
__global__ void __launch_bounds__(256) k_transpose(float* __restrict__ out) {
    __shared__ float s[CC][36];
    const int v0 = blockIdx.x * 32;
    const int t = threadIdx.x;
#pragma unroll
    for (int i = 0; i < 2; ++i) {
        int idx = t + i * 256;
        int cq = idx & 15, v = idx >> 4;
        float4 val = reinterpret_cast<const float4*>(g_bev)[(v0 + v) * 16 + cq];
        s[4 * cq + 0][v] = val.x;
        s[4 * cq + 1][v] = val.y;
        s[4 * cq + 2][v] = val.z;
        s[4 * cq + 3][v] = val.w;
    }
    __syncthreads();
#pragma unroll
    for (int i = 0; i < 2; ++i) {
        int idx = t + i * 256;
        int c = idx >> 3, w = idx & 7;
        float4 val = *reinterpret_cast<const float4*>(&s[c][4 * w]);
        reinterpret_cast<float4*>(out)[c * (NVOX / 4) + (v0 >> 2) + w] = val;
    }
}

extern "C" void kernel_launch(void* const* d_in, const int* in_sizes, int n_in,
                              void* d_out, int out_size) {
    const float* x          = (const float*)d_in[0];
    const float* rots       = (const float*)d_in[1];
    const float* trans      = (const float*)d_in[2];
    const float* intrins    = (const float*)d_in[3];
    const float* post_rots  = (const float*)d_in[4];
    const float* post_trans = (const float*)d_in[5];
    const float* w_depth    = (const float*)d_in[6];
    const float* b_depth    = (const float*)d_in[7];
    float* out = (float*)d_out;

    cudaFuncSetAttribute(k_feats, cudaFuncAttributeMaxDynamicSharedMemorySize,
                         FEATS_SMEM);

    k_zero<<<1024, 256>>>();
    k_feats<<<NPIX / 128, 256, FEATS_SMEM>>>(x, w_depth, b_depth);
    k_scatter<<<NPIX / 4, 128>>>(rots, trans, intrins, post_rots, post_trans);
    k_transpose<<<NVOX / 32, 256>>>(out);
}